// round 6
// baseline (speedup 1.0000x reference)
#include <cuda_runtime.h>
#include <cuda_fp16.h>
#include <math.h>

#define FIN 128
#define HID 64
#define N_MAX 100032
#define LRELU_ALPHA 0.2f

// ---- scratch (static device globals; no allocation allowed) ----
__device__ __half2 g_fts_h[(size_t)N_MAX * 32];  // seq@W as fp16 [N,64] 12.8MB (L2-resident)
__device__ float   g_f1[N_MAX];
__device__ float   g_f2[N_MAX];
__device__ int     g_rowptr[N_MAX + 1];

#define XT_STRIDE 132     // floats per k-row of transposed X tile
#define KSTAGE    64      // k rows resident per stage

// ============================================================================
// K1: seq_fts = seq @ W via packed fma.rn.f32x2 (FFMA2).
//   128-node x 64-hid tile per 256-thread block; K split into 2 stages so
//   smem = 32KB (Ws) + 34KB (Xt half) = 66KB -> 3 CTAs/SM (6 warps/SMSP).
//   Inner loop is explicitly software-pipelined (prefetch k+1 registers).
//   Fused epilogue: fp16 fts store + f1/f2 dots.
// ============================================================================
__global__ void __launch_bounds__(256, 3)
gemm_f12_kernel(const float* __restrict__ seq, const float* __restrict__ W,
                const float* __restrict__ a1, const float* __restrict__ b1,
                const float* __restrict__ a2, const float* __restrict__ b2,
                int N) {
    extern __shared__ float sm[];
    float* Ws = sm;                       // [128][64]   32KB (full K resident)
    float* Xt = sm + FIN * HID;           // [64][132]   34KB (half K, transposed)
    const int tid = threadIdx.x;
    const int n0 = blockIdx.x * 128;

    // load W (full, once)
    {
        const float4* W4 = (const float4*)W;
        float4* Ws4 = (float4*)Ws;
        #pragma unroll
        for (int i = tid; i < FIN * HID / 4; i += 256) Ws4[i] = W4[i];
    }

    const int tx = tid & 15;   // hid group: cols [tx*4, tx*4+4)
    const int ty = tid >> 4;   // node group: nodes [ty*8, ty*8+8) as 4 pairs

    unsigned bAddr = (unsigned)__cvta_generic_to_shared(Ws + tx * 4);
    unsigned aAddr = (unsigned)__cvta_generic_to_shared(Xt + ty * 8);

    unsigned long long acc[4][4];   // [node-pair][h]
    #pragma unroll
    for (int p = 0; p < 4; p++)
        #pragma unroll
        for (int h = 0; h < 4; h++) acc[p][h] = 0ull;

    for (int stage = 0; stage < 2; stage++) {
        // load this stage's X slice transposed: Xt[k - stage*64][node]
        __syncthreads();
        for (int i = tid; i < 128 * 16; i += 256) {
            int node = i & 127;
            int kk4 = (i >> 7) + stage * 16;    // float4 index within the 128-f row
            float4 v = make_float4(0.f, 0.f, 0.f, 0.f);
            if (n0 + node < N)
                v = ((const float4*)(seq + (size_t)(n0 + node) * FIN))[kk4];
            int kb = (kk4 - stage * 16) * 4;
            Xt[(kb + 0) * XT_STRIDE + node] = v.x;
            Xt[(kb + 1) * XT_STRIDE + node] = v.y;
            Xt[(kb + 2) * XT_STRIDE + node] = v.z;
            Xt[(kb + 3) * XT_STRIDE + node] = v.w;
        }
        __syncthreads();

        const unsigned bBase = bAddr + (unsigned)(stage * KSTAGE * HID * 4);

        // ---- software-pipelined inner loop over KSTAGE k's ----
        unsigned long long ca01, ca23, ca45, ca67;  // current A (node pairs)
        float4 cb;                                  // current B (4 hid cols)
        asm volatile("ld.shared.v2.u64 {%0,%1}, [%2];"
                     : "=l"(ca01), "=l"(ca23) : "r"(aAddr));
        asm volatile("ld.shared.v2.u64 {%0,%1}, [%2];"
                     : "=l"(ca45), "=l"(ca67) : "r"(aAddr + 16));
        asm volatile("ld.shared.v4.f32 {%0,%1,%2,%3}, [%4];"
                     : "=f"(cb.x), "=f"(cb.y), "=f"(cb.z), "=f"(cb.w) : "r"(bBase));

        #pragma unroll 4
        for (int k = 0; k < KSTAGE; k++) {
            unsigned long long na01, na23, na45, na67;
            float4 nb;
            if (k + 1 < KSTAGE) {
                unsigned ak = aAddr + (unsigned)((k + 1) * (XT_STRIDE * 4));
                asm volatile("ld.shared.v2.u64 {%0,%1}, [%2];"
                             : "=l"(na01), "=l"(na23) : "r"(ak));
                asm volatile("ld.shared.v2.u64 {%0,%1}, [%2];"
                             : "=l"(na45), "=l"(na67) : "r"(ak + 16));
                asm volatile("ld.shared.v4.f32 {%0,%1,%2,%3}, [%4];"
                             : "=f"(nb.x), "=f"(nb.y), "=f"(nb.z), "=f"(nb.w)
                             : "r"(bBase + (unsigned)((k + 1) * HID * 4)));
            }
            unsigned long long bb0, bb1, bb2, bb3;
            asm("mov.b64 %0, {%1,%1};" : "=l"(bb0) : "f"(cb.x));
            asm("mov.b64 %0, {%1,%1};" : "=l"(bb1) : "f"(cb.y));
            asm("mov.b64 %0, {%1,%1};" : "=l"(bb2) : "f"(cb.z));
            asm("mov.b64 %0, {%1,%1};" : "=l"(bb3) : "f"(cb.w));
            asm("fma.rn.f32x2 %0,%1,%2,%0;" : "+l"(acc[0][0]) : "l"(ca01), "l"(bb0));
            asm("fma.rn.f32x2 %0,%1,%2,%0;" : "+l"(acc[0][1]) : "l"(ca01), "l"(bb1));
            asm("fma.rn.f32x2 %0,%1,%2,%0;" : "+l"(acc[0][2]) : "l"(ca01), "l"(bb2));
            asm("fma.rn.f32x2 %0,%1,%2,%0;" : "+l"(acc[0][3]) : "l"(ca01), "l"(bb3));
            asm("fma.rn.f32x2 %0,%1,%2,%0;" : "+l"(acc[1][0]) : "l"(ca23), "l"(bb0));
            asm("fma.rn.f32x2 %0,%1,%2,%0;" : "+l"(acc[1][1]) : "l"(ca23), "l"(bb1));
            asm("fma.rn.f32x2 %0,%1,%2,%0;" : "+l"(acc[1][2]) : "l"(ca23), "l"(bb2));
            asm("fma.rn.f32x2 %0,%1,%2,%0;" : "+l"(acc[1][3]) : "l"(ca23), "l"(bb3));
            asm("fma.rn.f32x2 %0,%1,%2,%0;" : "+l"(acc[2][0]) : "l"(ca45), "l"(bb0));
            asm("fma.rn.f32x2 %0,%1,%2,%0;" : "+l"(acc[2][1]) : "l"(ca45), "l"(bb1));
            asm("fma.rn.f32x2 %0,%1,%2,%0;" : "+l"(acc[2][2]) : "l"(ca45), "l"(bb2));
            asm("fma.rn.f32x2 %0,%1,%2,%0;" : "+l"(acc[2][3]) : "l"(ca45), "l"(bb3));
            asm("fma.rn.f32x2 %0,%1,%2,%0;" : "+l"(acc[3][0]) : "l"(ca67), "l"(bb0));
            asm("fma.rn.f32x2 %0,%1,%2,%0;" : "+l"(acc[3][1]) : "l"(ca67), "l"(bb1));
            asm("fma.rn.f32x2 %0,%1,%2,%0;" : "+l"(acc[3][2]) : "l"(ca67), "l"(bb2));
            asm("fma.rn.f32x2 %0,%1,%2,%0;" : "+l"(acc[3][3]) : "l"(ca67), "l"(bb3));
            if (k + 1 < KSTAGE) {
                ca01 = na01; ca23 = na23; ca45 = na45; ca67 = na67; cb = nb;
            }
        }
    }

    // unpack: af[node 0..7][h 0..3]
    float af[8][4];
    #pragma unroll
    for (int p = 0; p < 4; p++)
        #pragma unroll
        for (int h = 0; h < 4; h++)
            asm("mov.b64 {%0,%1}, %2;"
                : "=f"(af[2 * p][h]), "=f"(af[2 * p + 1][h]) : "l"(acc[p][h]));

    // store fts as fp16
    #pragma unroll
    for (int i = 0; i < 8; i++) {
        int n = n0 + ty * 8 + i;
        if (n < N) {
            __half2 h0 = __floats2half2_rn(af[i][0], af[i][1]);
            __half2 h1 = __floats2half2_rn(af[i][2], af[i][3]);
            __half2* dst = g_fts_h + (size_t)n * 32 + tx * 2;
            dst[0] = h0;
            dst[1] = h1;
        }
    }

    // fused f1/f2 (fp32, from registers)
    float a1v0 = a1[tx * 4], a1v1 = a1[tx * 4 + 1], a1v2 = a1[tx * 4 + 2], a1v3 = a1[tx * 4 + 3];
    float a2v0 = a2[tx * 4], a2v1 = a2[tx * 4 + 1], a2v2 = a2[tx * 4 + 2], a2v3 = a2[tx * 4 + 3];
    float bb1s = b1[0], bb2s = b2[0];
    #pragma unroll
    for (int i = 0; i < 8; i++) {
        float p1 = af[i][0] * a1v0 + af[i][1] * a1v1 + af[i][2] * a1v2 + af[i][3] * a1v3;
        float p2 = af[i][0] * a2v0 + af[i][1] * a2v1 + af[i][2] * a2v2 + af[i][3] * a2v3;
        #pragma unroll
        for (int o = 8; o; o >>= 1) {
            p1 += __shfl_xor_sync(0xFFFFFFFFu, p1, o);
            p2 += __shfl_xor_sync(0xFFFFFFFFu, p2, o);
        }
        int n = n0 + ty * 8 + i;
        if (tx == 0 && n < N) {
            g_f1[n] = p1 + bb1s;
            g_f2[n] = p2 + bb2s;
        }
    }
}

// ============================================================================
// K2: CSR row_ptr from sorted edge_row
// ============================================================================
__global__ void build_rowptr(const int* __restrict__ erow, int E, int N) {
    int e = blockIdx.x * blockDim.x + threadIdx.x;
    if (e >= E) return;
    int r = erow[e];
    int rp = (e == 0) ? -1 : erow[e - 1];
    for (int rr = rp + 1; rr <= r; ++rr) g_rowptr[rr] = e;
    if (e == E - 1)
        for (int rr = r + 1; rr <= N; ++rr) g_rowptr[rr] = E;
}

// ============================================================================
// K3: fused logits + segmented softmax + SpMM + ELU. One warp per row.
//   Full 32-edge chunks: fully-unrolled 8-step gather (batched shfl+LDG,
//   MLP~16). Tail: ceil(t/4) steps with z=0 padding (correct: zero weight).
// ============================================================================
__device__ __forceinline__ void gather_step(int jj, int half, int li,
                                            int c, float z,
                                            float4& accA, float4& accB) {
    int sA = 4 * jj + half;
    int sB = sA + 2;
    int   cA = __shfl_sync(0xFFFFFFFFu, c, sA);
    float zA = __shfl_sync(0xFFFFFFFFu, z, sA);
    int   cB = __shfl_sync(0xFFFFFFFFu, c, sB);
    float zB = __shfl_sync(0xFFFFFFFFu, z, sB);
    uint2 rA = *(const uint2*)(g_fts_h + (size_t)cA * 32 + li * 2);
    uint2 rB = *(const uint2*)(g_fts_h + (size_t)cB * 32 + li * 2);
    float2 vA0 = __half22float2(*(__half2*)&rA.x);
    float2 vA1 = __half22float2(*(__half2*)&rA.y);
    float2 vB0 = __half22float2(*(__half2*)&rB.x);
    float2 vB1 = __half22float2(*(__half2*)&rB.y);
    accA.x += zA * vA0.x; accA.y += zA * vA0.y;
    accA.z += zA * vA1.x; accA.w += zA * vA1.y;
    accB.x += zB * vB0.x; accB.y += zB * vB0.y;
    accB.z += zB * vB1.x; accB.w += zB * vB1.y;
}

__global__ void __launch_bounds__(256)
attn_kernel(const int* __restrict__ ec, const float* __restrict__ ev,
            float* __restrict__ out, int N) {
    int row  = (blockIdx.x * 256 + threadIdx.x) >> 5;
    int lane = threadIdx.x & 31;
    if (row >= N) return;

    int s = g_rowptr[row];
    int e = g_rowptr[row + 1];
    float f1r = g_f1[row];

    const int half = lane >> 4;   // which edge of the pair this lane serves
    const int li   = lane & 15;   // 4-element slice (of 64) within the row

    float4 accA = make_float4(0.f, 0.f, 0.f, 0.f);
    float4 accB = make_float4(0.f, 0.f, 0.f, 0.f);
    float ssum = 0.f;

    int deg = e - s;
    int nfull = deg & ~31;

    // ---- full 32-edge chunks: straight-line body ----
    int base = s;
    for (; base < s + nfull; base += 32) {
        int idx = base + lane;
        int c = ec[idx];
        float l = ev[idx] * (f1r + g_f2[c]);
        l = fmaxf(l, LRELU_ALPHA * l);
        float z = __expf(l);
        ssum += z;
        #pragma unroll
        for (int jj = 0; jj < 8; jj++)
            gather_step(jj, half, li, c, z, accA, accB);
    }

    // ---- tail chunk (<32 edges), padded to multiple of 4 with z=0 ----
    int tail = deg & 31;
    if (tail) {
        int idx = base + lane;
        float z = 0.f;
        int c = 0;
        if (idx < e) {
            c = ec[idx];
            float l = ev[idx] * (f1r + g_f2[c]);
            l = fmaxf(l, LRELU_ALPHA * l);
            z = __expf(l);
        }
        ssum += z;
        int steps = (tail + 3) >> 2;
        for (int jj = 0; jj < steps; jj++)
            gather_step(jj, half, li, c, z, accA, accB);
    }

    float4 acc = make_float4(accA.x + accB.x, accA.y + accB.y,
                             accA.z + accB.z, accA.w + accB.w);
    acc.x += __shfl_xor_sync(0xFFFFFFFFu, acc.x, 16);
    acc.y += __shfl_xor_sync(0xFFFFFFFFu, acc.y, 16);
    acc.z += __shfl_xor_sync(0xFFFFFFFFu, acc.z, 16);
    acc.w += __shfl_xor_sync(0xFFFFFFFFu, acc.w, 16);
    #pragma unroll
    for (int o = 16; o; o >>= 1) ssum += __shfl_xor_sync(0xFFFFFFFFu, ssum, o);

    if (half == 0) {
        float4 o4 = make_float4(0.f, 0.f, 0.f, 0.f);
        if (deg > 0) {
            float inv = 1.f / ssum;
            o4 = make_float4(acc.x * inv, acc.y * inv, acc.z * inv, acc.w * inv);
        }
        o4.x = o4.x > 0.f ? o4.x : expm1f(o4.x);
        o4.y = o4.y > 0.f ? o4.y : expm1f(o4.y);
        o4.z = o4.z > 0.f ? o4.z : expm1f(o4.z);
        o4.w = o4.w > 0.f ? o4.w : expm1f(o4.w);
        *(float4*)(out + (size_t)row * HID + li * 4) = o4;
    }
}

// ============================================================================
// launch
// ============================================================================
extern "C" void kernel_launch(void* const* d_in, const int* in_sizes, int n_in,
                              void* d_out, int out_size) {
    const float* seq = (const float*)d_in[0];
    const int*   er  = (const int*)d_in[1];
    const int*   ec  = (const int*)d_in[2];
    const float* ev  = (const float*)d_in[3];
    const float* W   = (const float*)d_in[4];
    const float* a1  = (const float*)d_in[5];
    const float* b1  = (const float*)d_in[6];
    const float* a2  = (const float*)d_in[7];
    const float* b2  = (const float*)d_in[8];
    // d_in[9] = bias_zero (all zeros — no-op)
    float* out = (float*)d_out;

    int N = in_sizes[0] / FIN;   // seq is [1, N, 128]
    int E = in_sizes[1];

    const int SMEM = (FIN * HID + KSTAGE * XT_STRIDE) * (int)sizeof(float);  // ~66KB
    cudaFuncSetAttribute(gemm_f12_kernel,
                         cudaFuncAttributeMaxDynamicSharedMemorySize, SMEM);

    gemm_f12_kernel<<<(N + 127) / 128, 256, SMEM>>>(seq, W, a1, b1, a2, b2, N);
    build_rowptr<<<(E + 255) / 256, 256>>>(er, E, N);
    attn_kernel<<<(N + 7) / 8, 256>>>(ec, ev, out, N);
}